// round 10
// baseline (speedup 1.0000x reference)
#include <cuda_runtime.h>
#include <cstdint>

#define TAGS       10
#define SEQ        512
#define BATCHN     8192
#define START_TAG  8
#define STOP_TAG   9

#define QD         4                  // register-queue depth (timesteps ahead)

// Backpointers: u32 per (t,b); tag n (0..7) argmax nibble at bits 4n. 16.8 MB.
// t=0 never stored / never read (reference discards the t=0 carry).
__device__ unsigned g_bp[(size_t)SEQ * BATCHN];

// tournament node: value max + first-index argmax (left wins ties; exact compares)
#define TOURN(vl, il, vr, ir, mo, io) \
    { bool _p = (vr) > (vl); mo = _p ? (vr) : (vl); io = _p ? (ir) : (il); }

__device__ __forceinline__ void load_row8(float f[8], const char* p) {
    // row base = b*40 (+t*327680): 8-byte aligned for any b -> 4x LDG.64
    float2 a = __ldg((const float2*)(p));
    float2 b = __ldg((const float2*)(p + 8));
    float2 c = __ldg((const float2*)(p + 16));
    float2 d = __ldg((const float2*)(p + 24));
    f[0] = a.x; f[1] = a.y; f[2] = b.x; f[3] = b.y;
    f[4] = c.x; f[5] = c.y; f[6] = d.x; f[7] = d.y;
}

__global__ __launch_bounds__(32, 1)
void crf_viterbi10(const float* __restrict__ feats,
                   const float* __restrict__ trans,
                   float* __restrict__ out) {
    const int lane = threadIdx.x;
    const int b    = blockIdx.x * 32 + lane;

    const char*  fbase = (const char*)feats + (size_t)b * (TAGS * 4);
    const size_t gstep = (size_t)BATCHN * TAGS * 4;

    // transitions: 8x8 core, START column (t=0), STOP row (terminal)
    float Tm[8][8], Tc8[8], Ts9[8];
#pragma unroll
    for (int n = 0; n < 8; n++) {
#pragma unroll
        for (int p = 0; p < 8; p++) Tm[n][p] = __ldg(trans + n * TAGS + p);
        Tc8[n] = __ldg(trans + n * TAGS + START_TAG);
        Ts9[n] = __ldg(trans + STOP_TAG * TAGS + n);
    }

    unsigned* __restrict__ bp = g_bp + b;
    float fv[8];

    // register queue: prefetch t = 0..3
    float q[QD][8];
#pragma unroll
    for (int s = 0; s < QD; s++)
        load_row8(q[s], fbase + (size_t)s * gstep);

    // ---- one recurrence step (t>=1): consumes f[8], updates fv, stores bp ----
#define STEP(t, f)                                                         \
    {                                                                      \
        float nf[8];                                                       \
        unsigned bits = 0u;                                                \
        _Pragma("unroll")                                                  \
        for (int n = 0; n < 8; n++) {                                      \
            float v0 = fv[0] + Tm[n][0], v1 = fv[1] + Tm[n][1];            \
            float v2 = fv[2] + Tm[n][2], v3 = fv[3] + Tm[n][3];            \
            float v4 = fv[4] + Tm[n][4], v5 = fv[5] + Tm[n][5];            \
            float v6 = fv[6] + Tm[n][6], v7 = fv[7] + Tm[n][7];            \
            float a0, a1, a2, a3, c0, c1, m;                               \
            int   j0, j1, j2, j3, p0, p1, bi;                              \
            TOURN(v0, 0, v1, 1, a0, j0);                                   \
            TOURN(v2, 2, v3, 3, a1, j1);                                   \
            TOURN(v4, 4, v5, 5, a2, j2);                                   \
            TOURN(v6, 6, v7, 7, a3, j3);                                   \
            TOURN(a0, j0, a1, j1, c0, p0);                                 \
            TOURN(a2, j2, a3, j3, c1, p1);                                 \
            TOURN(c0, p0, c1, p1, m,  bi);                                 \
            nf[n] = m + (f)[n];                                            \
            bits |= (unsigned)bi << (4 * n);                               \
        }                                                                  \
        _Pragma("unroll")                                                  \
        for (int n = 0; n < 8; n++) fv[n] = nf[n];                         \
        bp[(size_t)(t) * BATCHN] = bits;                                   \
    }

    // peeled t=0 (winner prev is START, exactly): fv = T[n][START] + feat0[n]
#pragma unroll
    for (int n = 0; n < 8; n++) fv[n] = Tc8[n] + q[0][n];
    load_row8(q[0], fbase + (size_t)QD * gstep);          // t=4 -> slot 0

    // peeled t=1..3
    STEP(1, q[1]); load_row8(q[1], fbase + (size_t)(QD + 1) * gstep);
    STEP(2, q[2]); load_row8(q[2], fbase + (size_t)(QD + 2) * gstep);
    STEP(3, q[3]); load_row8(q[3], fbase + (size_t)(QD + 3) * gstep);

    // main loop: t = 4..511, queue slot = t & 3, prefetch t+4
    for (int tb = QD; tb < SEQ; tb += QD) {
#pragma unroll
        for (int s = 0; s < QD; s++) {
            const int t = tb + s;
            STEP(t, q[s]);
            const int nt = t + QD;
            if (nt < SEQ)
                load_row8(q[s], fbase + (size_t)nt * gstep);
        }
    }

    // terminal over next-tags 0..7 (8,9 provably never win)
    float tv[8];
#pragma unroll
    for (int n = 0; n < 8; n++) tv[n] = fv[n] + Ts9[n];
    float a0, a1, a2, a3, c0, c1, m;
    int   j0, j1, j2, j3, p0, p1, tag;
    TOURN(tv[0], 0, tv[1], 1, a0, j0);
    TOURN(tv[2], 2, tv[3], 3, a1, j1);
    TOURN(tv[4], 4, tv[5], 5, a2, j2);
    TOURN(tv[6], 6, tv[7], 7, a3, j3);
    TOURN(a0, j0, a1, j1, c0, p0);
    TOURN(a2, j2, a3, j3, c1, p1);
    TOURN(c0, p0, c1, p1, m,  tag);

    out[b] = m;
    float* __restrict__ path = out + BATCHN;

    // backtrace: t=511..1 reads bp[t]; path[0] = final carry (bp[0] never read)
#pragma unroll 16
    for (int t = SEQ - 1; t >= 1; t--) {
        path[(size_t)t * BATCHN + b] = (float)tag;
        const unsigned w = bp[(size_t)t * BATCHN];
        tag = (int)((w >> (4 * tag)) & 0xFu);
    }
    path[b] = (float)tag;

#undef STEP
}

extern "C" void kernel_launch(void* const* d_in, const int* in_sizes, int n_in,
                              void* d_out, int out_size) {
    const float* feats = (const float*)d_in[0];
    const float* trans = (const float*)d_in[1];
    float* out = (float*)d_out;

    // 256 blocks x 32 threads: one element per thread, pure-register pipeline
    crf_viterbi10<<<BATCHN / 32, 32>>>(feats, trans, out);
}

// round 11
// speedup vs baseline: 1.3470x; 1.3470x over previous
#include <cuda_runtime.h>
#include <cstdint>

#define TAGS       10
#define SEQ        512
#define BATCHN     8192
#define START_TAG  8
#define STOP_TAG   9

#define QD         4                  // LDG register-queue depth (timesteps)
#define WPB        8                  // warps per block
#define EPWRP      8                  // elements per warp (4 lanes each)
#define EPB        (WPB * EPWRP)      // 64 elements per block

// Backpointers: u32 per (t,b); tag n (0..7) nibble at bits 4n (byte n>>1,
// nibble n&1 -> written bytewise by lane q as (b0 | b1<<4)). 16.8 MB.
__device__ unsigned g_bp[(size_t)SEQ * BATCHN];

// tournament node: value max + first-index argmax (left wins ties; exact compares)
#define TOURN(vl, il, vr, ir, mo, io) \
    { bool _p = (vr) > (vl); mo = _p ? (vr) : (vl); io = _p ? (ir) : (il); }

// max+argmax over v[0..7] (ascending index order -> first-index ties)
#define TOURN8(v, M, BI)                                                  \
    {                                                                     \
        float _a0, _a1, _a2, _a3, _c0, _c1;                               \
        int _j0, _j1, _j2, _j3, _p0, _p1;                                 \
        TOURN(v[0], 0, v[1], 1, _a0, _j0);                                \
        TOURN(v[2], 2, v[3], 3, _a1, _j1);                                \
        TOURN(v[4], 4, v[5], 5, _a2, _j2);                                \
        TOURN(v[6], 6, v[7], 7, _a3, _j3);                                \
        TOURN(_a0, _j0, _a1, _j1, _c0, _p0);                              \
        TOURN(_a2, _j2, _a3, _j3, _c1, _p1);                              \
        TOURN(_c0, _p0, _c1, _p1, M, BI);                                 \
    }

__global__ __launch_bounds__(256, 1)
void crf_viterbi11(const float* __restrict__ feats,
                   const float* __restrict__ trans,
                   float* __restrict__ out) {
    // fv exchange: per warp, 2 parity regions x 8 elems x 48B (12 floats).
    // 48B element stride -> the two LDS.128 per lane are bank-conflict-free.
    __shared__ __align__(16) float xch[WPB][2][EPWRP][12];

    const int tid  = threadIdx.x;
    const int warp = tid >> 5;
    const int lane = tid & 31;
    const int e    = lane >> 2;          // element within warp (0..7)
    const int q    = lane & 3;           // tag pair: handles tags 2q, 2q+1
    const int n0   = 2 * q, n1 = 2 * q + 1;
    const int b    = blockIdx.x * EPB + warp * EPWRP + e;

    // my 2 feat values live at row + 8q (8-byte aligned for any b)
    const char*  fbase = (const char*)feats + (size_t)b * (TAGS * 4) + 8 * q;
    const size_t gstep = (size_t)BATCHN * TAGS * 4;

    // transitions: my 2 rows (prevs 0..7), START column pair, STOP row pair
    float T0[8], T1[8];
#pragma unroll
    for (int p = 0; p < 8; p++) {
        T0[p] = __ldg(trans + n0 * TAGS + p);
        T1[p] = __ldg(trans + n1 * TAGS + p);
    }
    const float Tc0 = __ldg(trans + n0 * TAGS + START_TAG);
    const float Tc1 = __ldg(trans + n1 * TAGS + START_TAG);
    const float Ts0 = __ldg(trans + STOP_TAG * TAGS + n0);
    const float Ts1 = __ldg(trans + STOP_TAG * TAGS + n1);

    // per-step bp byte pointer: byte q of u32 record (t*BATCHN + b)
    char* pbp = (char*)g_bp + 4 * ((size_t)b) + q;

    float* __restrict__ myslot0 = &xch[warp][0][e][2 * q];
    float* __restrict__ myslot1 = &xch[warp][1][e][2 * q];
    const float4* __restrict__ rd0 = (const float4*)&xch[warp][0][e][0];
    const float4* __restrict__ rd1 = (const float4*)&xch[warp][1][e][0];

    // LDG register queue: t = 0..QD-1
    float2 fq[QD];
#pragma unroll
    for (int s = 0; s < QD; s++)
        fq[s] = __ldg((const float2*)(fbase + (size_t)s * gstep));

    float fv[8];

    // ---- one step (t>=1): parity P, queue slot S ----
#define STEP(t, S, P)                                                     \
    {                                                                     \
        float v0[8], v1[8];                                               \
        _Pragma("unroll")                                                 \
        for (int p = 0; p < 8; p++) { v0[p] = fv[p] + T0[p];              \
                                      v1[p] = fv[p] + T1[p]; }            \
        float m0, m1; int b0, b1;                                         \
        TOURN8(v0, m0, b0);                                               \
        TOURN8(v1, m1, b1);                                               \
        const float nf0 = m0 + fq[S].x;                                   \
        const float nf1 = m1 + fq[S].y;                                   \
        *pbp = (char)(b0 | (b1 << 4));                                    \
        pbp += 4 * (size_t)BATCHN;                                        \
        if ((t) + QD < SEQ)                                               \
            fq[S] = __ldg((const float2*)(fbase + (size_t)((t) + QD) * gstep)); \
        float* sl = (P) ? myslot1 : myslot0;                              \
        sl[0] = nf0; sl[1] = nf1;                                         \
        __syncwarp();                                                     \
        const float4* rp = (P) ? rd1 : rd0;                               \
        float4 lo = rp[0], hi = rp[1];                                    \
        fv[0] = lo.x; fv[1] = lo.y; fv[2] = lo.z; fv[3] = lo.w;           \
        fv[4] = hi.x; fv[5] = hi.y; fv[6] = hi.z; fv[7] = hi.w;           \
    }

    // ---- peeled t=0 (winner prev is START, exact): nf = Tc + feat0 ----
    {
        const float nf0 = Tc0 + fq[0].x;
        const float nf1 = Tc1 + fq[0].y;
        fq[0] = __ldg((const float2*)(fbase + (size_t)QD * gstep));
        myslot0[0] = nf0; myslot0[1] = nf1;
        __syncwarp();
        float4 lo = rd0[0], hi = rd0[1];
        fv[0] = lo.x; fv[1] = lo.y; fv[2] = lo.z; fv[3] = lo.w;
        fv[4] = hi.x; fv[5] = hi.y; fv[6] = hi.z; fv[7] = hi.w;
        pbp += 4 * (size_t)BATCHN;          // skip t=0 record (never read)
    }

    // peeled t = 1..3 (parity = t&1, slot = t&3)
    STEP(1, 1, 1);
    STEP(2, 2, 0);
    STEP(3, 3, 1);

    // main loop: t = 4..511
    for (int tb = QD; tb < SEQ; tb += QD) {
        STEP(tb + 0, 0, 0);
        STEP(tb + 1, 1, 1);
        STEP(tb + 2, 2, 0);
        STEP(tb + 3, 3, 1);
    }
#undef STEP

    // ---- terminal: max/argmax over 8 tags via smem pairs ----
    {
        float tv0 = fv[n0] + Ts0, tv1 = fv[n1] + Ts1;
        float lm; int lt;
        { bool _p = tv1 > tv0; lm = _p ? tv1 : tv0; lt = _p ? n1 : n0; }
        // store (m, tag) per lane at parity 0 region (loop done; safe)
        myslot0[0] = lm; myslot0[1] = __int_as_float(lt);
        __syncwarp();
        if (q == 0) {
            float4 lo = rd0[0], hi = rd0[1];
            float mv[4] = { lo.x, lo.z, hi.x, hi.z };
            int   mt[4] = { __float_as_int(lo.y), __float_as_int(lo.w),
                            __float_as_int(hi.y), __float_as_int(hi.w) };
            float a0, a1, m; int t0, t1, tag;
            TOURN(mv[0], mt[0], mv[1], mt[1], a0, t0);
            TOURN(mv[2], mt[2], mv[3], mt[3], a1, t1);
            TOURN(a0, t0, a1, t1, m, tag);

            out[b] = m;
            float* __restrict__ path = out + BATCHN;
            const unsigned* __restrict__ rec = g_bp + b;
#pragma unroll 16
            for (int t = SEQ - 1; t >= 1; t--) {
                path[(size_t)t * BATCHN + b] = (float)tag;
                const unsigned w = rec[(size_t)t * BATCHN];
                tag = (int)((w >> (4 * tag)) & 0xFu);
            }
            path[b] = (float)tag;
        }
    }
}

extern "C" void kernel_launch(void* const* d_in, const int* in_sizes, int n_in,
                              void* d_out, int out_size) {
    const float* feats = (const float*)d_in[0];
    const float* trans = (const float*)d_in[1];
    float* out = (float*)d_out;

    // 128 blocks x 256 threads = 1024 warps, 8 elements per warp, no SHFL
    crf_viterbi11<<<BATCHN / EPB, 256>>>(feats, trans, out);
}

// round 12
// speedup vs baseline: 1.3772x; 1.0224x over previous
#include <cuda_runtime.h>
#include <cstdint>

#define TAGS       10
#define SEQ        512
#define BATCHN     8192
#define START_TAG  8
#define STOP_TAG   9

#define QD         8                   // LDG register-queue depth (timesteps)
#define WPB        4                   // warps per block
#define EPWRP      4                   // elements per warp (8 lanes each)
#define EPB        (WPB * EPWRP)       // 16 elements per block

// Backpointers: u32 per (t,b); tag n (0..7) nibble at bits 4n. 16.8 MB.
// t=0 never stored / never read (reference discards the t=0 carry).
__device__ unsigned g_bp[(size_t)SEQ * BATCHN];

// tournament node: value max + first-index argmax (left wins ties; exact compares)
#define TOURN(vl, il, vr, ir, mo, io) \
    { bool _p = (vr) > (vl); mo = _p ? (vr) : (vl); io = _p ? (ir) : (il); }

// max+argmax over v[0..7], ascending index order -> first-index ties
#define TOURN8(v, M, BI)                                                  \
    {                                                                     \
        float _a0, _a1, _a2, _a3, _c0, _c1;                               \
        int _j0, _j1, _j2, _j3, _p0, _p1;                                 \
        TOURN(v[0], 0, v[1], 1, _a0, _j0);                                \
        TOURN(v[2], 2, v[3], 3, _a1, _j1);                                \
        TOURN(v[4], 4, v[5], 5, _a2, _j2);                                \
        TOURN(v[6], 6, v[7], 7, _a3, _j3);                                \
        TOURN(_a0, _j0, _a1, _j1, _c0, _p0);                              \
        TOURN(_a2, _j2, _a3, _j3, _c1, _p1);                              \
        TOURN(_c0, _p0, _c1, _p1, M, BI);                                 \
    }

__global__ __launch_bounds__(128, 1)
void crf_viterbi12(const float* __restrict__ feats,
                   const float* __restrict__ trans,
                   float* __restrict__ out) {
    // fv exchange: per warp, 2 parity buffers x 4 elems x 8 floats = 256 B/warp.
    // STS: 32 consecutive words (conflict-free). LDS.128: 4 distinct 16B addrs,
    // 8-lane broadcast each (conflict-free).
    __shared__ __align__(16) float xch[WPB][2][EPWRP][8];

    const int tid  = threadIdx.x;
    const int warp = tid >> 5;
    const int lane = tid & 31;
    const int e    = lane >> 3;          // element within warp (0..3)
    const int n    = lane & 7;           // my next-tag (0..7)
    const int b    = blockIdx.x * EPB + warp * EPWRP + e;

    // my single feat value per step: feats[t][b][n]
    const char*  fbase = (const char*)feats + (size_t)b * (TAGS * 4) + 4 * n;
    const size_t gstep = (size_t)BATCHN * TAGS * 4;

    // transitions: my row (prevs 0..7), START column entry, STOP row entry
    float T[8];
#pragma unroll
    for (int p = 0; p < 8; p++) T[p] = __ldg(trans + n * TAGS + p);
    const float Tc = __ldg(trans + n * TAGS + START_TAG);
    const float Ts = __ldg(trans + STOP_TAG * TAGS + n);

    // bp byte pointer: byte n>>1 of u32 record (t*BATCHN + b); even n stores
    char* pbp = (char*)g_bp + 4 * ((size_t)b) + (n >> 1);
    const bool bp_lane = ((n & 1) == 0);

    float* __restrict__ w0 = &xch[warp][0][e][n];
    float* __restrict__ w1 = &xch[warp][1][e][n];
    const float4* __restrict__ r0 = (const float4*)&xch[warp][0][e][0];
    const float4* __restrict__ r1 = (const float4*)&xch[warp][1][e][0];

    // LDG register queue: t = 0..QD-1
    float fq[QD];
#pragma unroll
    for (int s = 0; s < QD; s++)
        fq[s] = __ldg((const float*)(fbase + (size_t)s * gstep));

    float fv[8];

    // ---- one step (t>=1): queue slot S = t&7, parity P = t&1 ----
#define STEP(t, S, P)                                                     \
    {                                                                     \
        float v[8];                                                       \
        _Pragma("unroll")                                                 \
        for (int p = 0; p < 8; p++) v[p] = fv[p] + T[p];                  \
        float m; int bi;                                                  \
        TOURN8(v, m, bi);                                                 \
        const float nf = m + fq[S];                                       \
        if ((t) + QD < SEQ)                                               \
            fq[S] = __ldg((const float*)(fbase + (size_t)((t) + QD) * gstep)); \
        const int bj = bi | (__shfl_down_sync(0xffffffffu, bi, 1) << 4);  \
        if (bp_lane) *pbp = (char)bj;                                     \
        pbp += 4 * (size_t)BATCHN;                                        \
        *((P) ? w1 : w0) = nf;                                            \
        __syncwarp();                                                     \
        const float4* rp = (P) ? r1 : r0;                                 \
        float4 lo = rp[0], hi = rp[1];                                    \
        fv[0] = lo.x; fv[1] = lo.y; fv[2] = lo.z; fv[3] = lo.w;           \
        fv[4] = hi.x; fv[5] = hi.y; fv[6] = hi.z; fv[7] = hi.w;           \
    }

    // ---- peeled t=0 (winner prev is START, exact): nf = Tc + feat0 ----
    {
        const float nf = Tc + fq[0];
        fq[0] = __ldg((const float*)(fbase + (size_t)QD * gstep));
        *w0 = nf;
        __syncwarp();
        float4 lo = r0[0], hi = r0[1];
        fv[0] = lo.x; fv[1] = lo.y; fv[2] = lo.z; fv[3] = lo.w;
        fv[4] = hi.x; fv[5] = hi.y; fv[6] = hi.z; fv[7] = hi.w;
        pbp += 4 * (size_t)BATCHN;           // skip t=0 record (never read)
    }

    // peeled t = 1..7
    STEP(1, 1, 1); STEP(2, 2, 0); STEP(3, 3, 1);
    STEP(4, 4, 0); STEP(5, 5, 1); STEP(6, 6, 0); STEP(7, 7, 1);

    // main loop: t = 8..511
    for (int tb = QD; tb < SEQ; tb += QD) {
        STEP(tb + 0, 0, 0); STEP(tb + 1, 1, 1);
        STEP(tb + 2, 2, 0); STEP(tb + 3, 3, 1);
        STEP(tb + 4, 4, 0); STEP(tb + 5, 5, 1);
        STEP(tb + 6, 6, 0); STEP(tb + 7, 7, 1);
    }
#undef STEP

    // ---- terminal: tv = fv[n] + Ts per lane; exchange; lane n==0 reduces ----
    {
        const float tv = fv[n] + Ts;
        *w0 = tv;                            // parity-0 buffer, loop finished
        __syncwarp();
        if (n == 0) {
            float4 lo = r0[0], hi = r0[1];
            float tvv[8] = { lo.x, lo.y, lo.z, lo.w, hi.x, hi.y, hi.z, hi.w };
            float m; int tag;
            TOURN8(tvv, m, tag);

            out[b] = m;
            float* __restrict__ path = out + BATCHN;
            const unsigned* __restrict__ rec = g_bp + b;
#pragma unroll 16
            for (int t = SEQ - 1; t >= 1; t--) {
                path[(size_t)t * BATCHN + b] = (float)tag;
                const unsigned w = rec[(size_t)t * BATCHN];
                tag = (int)((w >> (4 * tag)) & 0xFu);
            }
            path[b] = (float)tag;
        }
    }
}

extern "C" void kernel_launch(void* const* d_in, const int* in_sizes, int n_in,
                              void* d_out, int out_size) {
    const float* feats = (const float*)d_in[0];
    const float* trans = (const float*)d_in[1];
    float* out = (float*)d_out;

    // 512 blocks x 128 threads = 2048 warps (~14/SM): 8 lanes per element
    crf_viterbi12<<<BATCHN / EPB, 128>>>(feats, trans, out);
}

// round 13
// speedup vs baseline: 1.4537x; 1.0556x over previous
#include <cuda_runtime.h>
#include <cstdint>

#define TAGS       10
#define SEQ        512
#define BATCHN     8192
#define START_TAG  8
#define STOP_TAG   9

#define TBLK       4                        // timesteps per pipeline stage
#define NBLK       (SEQ / TBLK)             // 128 time-blocks
#define STAGES     4
#define EPW        16                       // batch elems per warp
#define TSB        (EPW * TAGS * 4)         // 640 B per warp per timestep
#define WPB        4
#define BPB        (EPW * WPB)              // 64 elems per block

// Backpointers: u32 per (t,b); tag n (0..7) argmax nibble at bits 4n. 16.8 MB.
// t=0 never stored / never read (reference discards the t=0 carry).
__device__ unsigned g_bp[(size_t)SEQ * BATCHN];

__device__ __forceinline__ void cp16(uint32_t s, const void* g) {
    asm volatile("cp.async.ca.shared.global [%0], [%1], 16;\n" :: "r"(s), "l"(g));
}
__device__ __forceinline__ void cp_commit() {
    asm volatile("cp.async.commit_group;\n" ::: "memory");
}
__device__ __forceinline__ void cp_wait2() {
    asm volatile("cp.async.wait_group 2;\n" ::: "memory");
}

// tournament node, tie -> left (first index)
#define TOURN(vl, il, vr, ir, mo, io) \
    { bool _p = (vr) > (vl); mo = _p ? (vr) : (vl); io = _p ? (ir) : (il); }
// final-level node: tie -> right iff hb (restores absolute-index tie order
// under the half-swap permutation); exact compares
#define TOURNF(vl, il, vr, ir, hb, mo, io)                                 \
    { bool _p = ((vr) > (vl)) || (((vr) == (vl)) && (hb));                 \
      mo = _p ? (vr) : (vl); io = _p ? (ir) : (il); }

__global__ __launch_bounds__(128, 1)
void crf_viterbi13(const float* __restrict__ feats,
                   const float* __restrict__ trans,
                   float* __restrict__ out) {
    // warp-private rings: 4 warps x 4 stages x (4 ts x 640 B) = 40 KB
    __shared__ __align__(16) char ring[WPB][STAGES][TBLK * TSB];

    const int tid  = threadIdx.x;
    const int warp = tid >> 5;
    const int lane = tid & 31;
    const int lb   = lane >> 1;          // local elem 0..15
    const int h    = lane & 1;           // half-swap: lane owns abs tags 4h..4h+3
    const bool hb  = (h != 0);
    const int b    = blockIdx.x * BPB + warp * EPW + lb;

    const char*  gbase = (const char*)feats +
                         ((size_t)blockIdx.x * BPB + (size_t)warp * EPW) * (TAGS * 4);
    const size_t gstep = (size_t)BATCHN * TAGS * 4;
    const bool has_c1 = (lane < 8);

    uint32_t s_ring0;
    asm("{ .reg .u64 t; cvta.to.shared.u64 t, %1; cvt.u32.u64 %0, t; }"
        : "=r"(s_ring0) : "l"(&ring[warp][0][0]));

    // permuted transition block: row/col r = (x + 4h) & 7
    // Tm[i][j] = trans[r_i][r_j]; Tc[i] = trans[r_i][START]; Ts = STOP row (abs,
    // used only on h==0 where the permutation is identity).
    float Tm[8][8], Tc[8], Ts[8];
#pragma unroll
    for (int i = 0; i < 8; i++) {
        const int ri = (i + 4 * h) & 7;
#pragma unroll
        for (int j = 0; j < 8; j++)
            Tm[i][j] = __ldg(trans + ri * TAGS + ((j + 4 * h) & 7));
        Tc[i] = __ldg(trans + ri * TAGS + START_TAG);
        Ts[i] = __ldg(trans + STOP_TAG * TAGS + i);
    }

    // prologue: fill stages 0..2 (one commit group per time-block)
#pragma unroll
    for (int s = 0; s < STAGES - 1; s++) {
        uint32_t sb = s_ring0 + s * (TBLK * TSB);
#pragma unroll
        for (int k = 0; k < TBLK; k++) {
            const char* g = gbase + (size_t)(s * TBLK + k) * gstep;
            cp16(sb + k * TSB + lane * 16, g + lane * 16);
            if (has_c1) cp16(sb + k * TSB + (32 + lane) * 16, g + (32 + lane) * 16);
        }
        cp_commit();
    }

    // feat read offsets: swap the two 16B halves for h=1 so f[] lands in
    // permuted order with zero per-step cost (4x LDS.64, all 8B-aligned)
    const int offA = lb * 40 + (h ? 16 : 0);   // perm tags 0..3
    const int offB = lb * 40 + (h ? 0 : 16);   // perm tags 4..7

    unsigned short* __restrict__ bp16 = (unsigned short*)g_bp;
    const unsigned xmask = h ? 0x4444u : 0u;

    float fv[8];          // state in PERMUTED coordinates (per lane)

    for (int ib = 0; ib < NBLK; ib++) {
        cp_wait2();
        __syncwarp();

        const char* sp = ring[warp][ib & (STAGES - 1)];

        // prefetch time-block ib+3 into the freed stage; always commit
        {
            const int nb = ib + STAGES - 1;
            if (nb < NBLK) {
                uint32_t sb = s_ring0 + (nb & (STAGES - 1)) * (TBLK * TSB);
#pragma unroll
                for (int k = 0; k < TBLK; k++) {
                    const char* g = gbase + (size_t)(nb * TBLK + k) * gstep;
                    cp16(sb + k * TSB + lane * 16, g + lane * 16);
                    if (has_c1)
                        cp16(sb + k * TSB + (32 + lane) * 16, g + (32 + lane) * 16);
                }
            }
            cp_commit();
        }

#pragma unroll
        for (int k = 0; k < TBLK; k++) {
            const int t = ib * TBLK + k;
            const char* sk = sp + k * TSB;
            float2 a0 = *(const float2*)(sk + offA);
            float2 a1 = *(const float2*)(sk + offA + 8);
            float2 b0 = *(const float2*)(sk + offB);
            float2 b1 = *(const float2*)(sk + offB + 8);
            float f[8] = { a0.x, a0.y, a1.x, a1.y, b0.x, b0.y, b1.x, b1.y };

            if (ib == 0 && k == 0) {
                // exact peeled t=0: winner prev is START for every tag
#pragma unroll
                for (int i = 0; i < 8; i++) fv[i] = Tc[i] + f[i];
                continue;
            }

            // owned tags = permuted rows 0..3: full max+argmax tournaments
            float nf[8];
            unsigned bits = 0u;
#pragma unroll
            for (int i = 0; i < 4; i++) {
                float v0 = fv[0] + Tm[i][0], v1 = fv[1] + Tm[i][1];
                float v2 = fv[2] + Tm[i][2], v3 = fv[3] + Tm[i][3];
                float v4 = fv[4] + Tm[i][4], v5 = fv[5] + Tm[i][5];
                float v6 = fv[6] + Tm[i][6], v7 = fv[7] + Tm[i][7];
                float a0_, a1_, a2_, a3_, c0_, c1_, m;
                int   j0, j1, j2, j3, p0, p1, bi;
                TOURN(v0, 0, v1, 1, a0_, j0);
                TOURN(v2, 2, v3, 3, a1_, j1);
                TOURN(v4, 4, v5, 5, a2_, j2);
                TOURN(v6, 6, v7, 7, a3_, j3);
                TOURN(a0_, j0, a1_, j1, c0_, p0);
                TOURN(a2_, j2, a3_, j3, c1_, p1);
                TOURNF(c0_, p0, c1_, p1, hb, m, bi);   // abs-order tie-break
                nf[i] = m + f[i];
                bits |= (unsigned)bi << (4 * i);
            }
            // foreign tags = permuted rows 4..7: value-only fmax trees
            // (fmax value == tournament value bitwise; no NaN)
#pragma unroll
            for (int i = 4; i < 8; i++) {
                float v0 = fv[0] + Tm[i][0], v1 = fv[1] + Tm[i][1];
                float v2 = fv[2] + Tm[i][2], v3 = fv[3] + Tm[i][3];
                float v4 = fv[4] + Tm[i][4], v5 = fv[5] + Tm[i][5];
                float v6 = fv[6] + Tm[i][6], v7 = fv[7] + Tm[i][7];
                float m = fmaxf(fmaxf(fmaxf(v0, v1), fmaxf(v2, v3)),
                                fmaxf(fmaxf(v4, v5), fmaxf(v6, v7)));
                nf[i] = m + f[i];
            }
#pragma unroll
            for (int i = 0; i < 8; i++) fv[i] = nf[i];

            // my u16: nibbles of abs tags 4h..4h+3 (xmask maps perm->abs prev)
            bp16[2 * ((size_t)t * BATCHN + b) + h] =
                (unsigned short)(bits ^ xmask);
        }
    }

    // terminal + backtrace on h==0 lanes (their permutation is identity)
    if (!hb) {
        float tv[8];
#pragma unroll
        for (int i = 0; i < 8; i++) tv[i] = fv[i] + Ts[i];
        float a0_, a1_, a2_, a3_, c0_, c1_, m;
        int   j0, j1, j2, j3, p0, p1, tag;
        TOURN(tv[0], 0, tv[1], 1, a0_, j0);
        TOURN(tv[2], 2, tv[3], 3, a1_, j1);
        TOURN(tv[4], 4, tv[5], 5, a2_, j2);
        TOURN(tv[6], 6, tv[7], 7, a3_, j3);
        TOURN(a0_, j0, a1_, j1, c0_, p0);
        TOURN(a2_, j2, a3_, j3, c1_, p1);
        TOURN(c0_, p0, c1_, p1, m, tag);

        out[b] = m;
        float* __restrict__ path = out + BATCHN;
        const unsigned* __restrict__ rec = g_bp + b;
#pragma unroll 16
        for (int t = SEQ - 1; t >= 1; t--) {
            path[(size_t)t * BATCHN + b] = (float)tag;
            const unsigned w = rec[(size_t)t * BATCHN];
            tag = (int)((w >> (4 * tag)) & 0xFu);
        }
        path[b] = (float)tag;
    }
}

extern "C" void kernel_launch(void* const* d_in, const int* in_sizes, int n_in,
                              void* d_out, int out_size) {
    const float* feats = (const float*)d_in[0];
    const float* trans = (const float*)d_in[1];
    float* out = (float*)d_out;

    crf_viterbi13<<<BATCHN / BPB, 128>>>(feats, trans, out);   // 128 blocks
}